// round 4
// baseline (speedup 1.0000x reference)
#include <cuda_runtime.h>
#include <cstdint>

// ============================================================================
// EdgeClassifier: out = relu([emb[h], emb[t]] @ W1^T + b1) @ W2^T + b2
// E=500000, D=128, HIDDEN=256, NUM_CLASSES=32, fp32 in/out.
// mma.sync.m16n8k8 tf32. R3: TILE_M=64 + KC=32 -> 103KB smem, 2 CTAs/SM.
// ============================================================================

#define TILE_M 64
#define DIMD   128
#define HID    256
#define NCLS   32
#define KC     32          // W1 K-chunk width

#define SAW 260            // A/A2 row stride (words): 260 % 32 == 4 -> conflict-free
#define SBW 36             // W1-chunk row stride:      36 % 32 == 4 -> conflict-free
#define SW2 268            // W2 row stride:           268 % 32 == 12 -> conflict-free

// SMEM byte offsets
#define SM_B1    0                              // 256 floats b1
#define SM_B2    1024                           // 32 floats b2
#define SM_A     2048                           // 64 x 260 u32 = 66560 B
#define SM_B     (SM_A + TILE_M * SAW * 4)      // max(256x36, 32x268) u32 = 36864 B
#define SM_TOTAL (SM_B + 256 * SBW * 4)         // 105472 B -> 2 CTAs/SM

__device__ int g_is64;

__device__ __forceinline__ uint32_t f2tf32(float f) {
    uint32_t r;
    asm("cvt.rna.tf32.f32 %0, %1;" : "=r"(r) : "f"(f));
    return r;
}

__device__ __forceinline__ void mma8(float* c, const uint32_t* a,
                                     uint32_t b0, uint32_t b1) {
    asm volatile(
        "mma.sync.aligned.m16n8k8.row.col.f32.tf32.tf32.f32 "
        "{%0,%1,%2,%3}, {%4,%5,%6,%7}, {%8,%9}, {%0,%1,%2,%3};"
        : "+f"(c[0]), "+f"(c[1]), "+f"(c[2]), "+f"(c[3])
        : "r"(a[0]), "r"(a[1]), "r"(a[2]), "r"(a[3]), "r"(b0), "r"(b1));
}

// Detect int64 vs int32 edge_index (high words all zero iff int64).
__global__ void detect_idx_kernel(const unsigned int* __restrict__ p) {
    unsigned int acc = 0;
    for (int i = 1; i < 256; i += 2) acc |= p[i];
    g_is64 = (acc == 0u) ? 1 : 0;
}

// ============================================================================
__global__ __launch_bounds__(256, 2)
void edge_mlp_kernel(const float* __restrict__ emb,
                     const void*  __restrict__ eidx,
                     const float* __restrict__ W1,
                     const float* __restrict__ b1,
                     const float* __restrict__ W2,
                     const float* __restrict__ b2,
                     float* __restrict__ out,
                     int E) {
    extern __shared__ char smem[];
    float*    sb1 = (float*)(smem + SM_B1);
    float*    sb2 = (float*)(smem + SM_B2);
    uint32_t* Asm = (uint32_t*)(smem + SM_A);
    uint32_t* Bsm = (uint32_t*)(smem + SM_B);

    const int tid  = threadIdx.x;
    const int wid  = tid >> 5;
    const int lane = tid & 31;
    const int g    = lane >> 2;   // 0..7
    const int t    = lane & 3;    // 0..3
    const int tile = blockIdx.x;
    const int is64 = g_is64;

    sb1[tid] = b1[tid];
    if (tid < NCLS) sb2[tid] = b2[tid];

    // ---- Gather A[64][256]: 128 row-halves ----
    for (int rh = wid; rh < 2 * TILE_M; rh += 8) {
        const int r = rh >> 1, half = rh & 1;
        const int e = tile * TILE_M + r;
        float4 v = make_float4(0.f, 0.f, 0.f, 0.f);
        if (e < E) {
            const long long ofs = half ? (long long)E + e : (long long)e;
            const long long node = is64 ? ((const long long*)eidx)[ofs]
                                        : (long long)((const int*)eidx)[ofs];
            v = ((const float4*)(emb + node * DIMD))[lane];
        }
        *(uint4*)(Asm + r * SAW + half * 128 + lane * 4) =
            make_uint4(f2tf32(v.x), f2tf32(v.y), f2tf32(v.z), f2tf32(v.w));
    }
    __syncthreads();

    // ---- GEMM1: D1[64,256] = A @ W1^T; warp tile 32x64 (2m x 4n warps) ----
    const int mbase = (wid & 1) * 32;
    const int nbase = (wid >> 1) * 64;

    float acc[2][8][4];
    #pragma unroll
    for (int mt = 0; mt < 2; mt++)
        #pragma unroll
        for (int nt = 0; nt < 8; nt++)
            #pragma unroll
            for (int j = 0; j < 4; j++) acc[mt][nt][j] = 0.f;

    #pragma unroll 1
    for (int kc = 0; kc < HID / KC; kc++) {
        // Stage W1[:, kc*KC .. +KC) -> Bsm (256 rows x 32 cols, tf32).
        {
            const float4* wrow = (const float4*)(W1 + tid * (2 * DIMD) + kc * KC);
            uint32_t* brow = Bsm + tid * SBW;
            #pragma unroll
            for (int j = 0; j < KC / 4; j++) {
                float4 w = wrow[j];
                *(uint4*)(brow + j * 4) = make_uint4(f2tf32(w.x), f2tf32(w.y),
                                                     f2tf32(w.z), f2tf32(w.w));
            }
        }
        __syncthreads();

        #pragma unroll
        for (int s = 0; s < KC / 8; s++) {
            const int k0 = s * 8;
            const int ka = kc * KC + k0;
            uint32_t af[2][4];
            #pragma unroll
            for (int mt = 0; mt < 2; mt++) {
                const int r = mbase + mt * 16;
                af[mt][0] = Asm[(r + g)     * SAW + ka + t];
                af[mt][1] = Asm[(r + g + 8) * SAW + ka + t];
                af[mt][2] = Asm[(r + g)     * SAW + ka + t + 4];
                af[mt][3] = Asm[(r + g + 8) * SAW + ka + t + 4];
            }
            #pragma unroll
            for (int nt = 0; nt < 8; nt++) {
                const int n = nbase + nt * 8 + g;
                const uint32_t b0  = Bsm[n * SBW + k0 + t];
                const uint32_t b1r = Bsm[n * SBW + k0 + t + 4];
                mma8(acc[0][nt], af[0], b0, b1r);
                mma8(acc[1][nt], af[1], b0, b1r);
            }
        }
        __syncthreads();
    }

    // ---- Epilogue1: A2 = tf32(relu(D1 + b1)) in place over A ----
    #pragma unroll
    for (int mt = 0; mt < 2; mt++) {
        #pragma unroll
        for (int nt = 0; nt < 8; nt++) {
            const int r0  = mbase + mt * 16 + g;
            const int col = nbase + nt * 8 + t * 2;
            const float bi0 = sb1[col], bi1 = sb1[col + 1];
            float* c = acc[mt][nt];
            uint2 lo, hi;
            lo.x = f2tf32(fmaxf(c[0] + bi0, 0.f));
            lo.y = f2tf32(fmaxf(c[1] + bi1, 0.f));
            hi.x = f2tf32(fmaxf(c[2] + bi0, 0.f));
            hi.y = f2tf32(fmaxf(c[3] + bi1, 0.f));
            *(uint2*)(Asm + r0 * SAW + col)       = lo;
            *(uint2*)(Asm + (r0 + 8) * SAW + col) = hi;
        }
    }
    // Stage W2[32][256] -> Bsm, stride SW2, tf32.
    {
        const int rw = tid >> 3;                 // 0..31
        const int cj = tid & 7;                  // 0..7
        #pragma unroll
        for (int j = 0; j < 8; j++) {
            float4 w = *(const float4*)(W2 + rw * HID + (j * 8 + cj) * 4);
            *(uint4*)(Bsm + rw * SW2 + (j * 8 + cj) * 4) =
                make_uint4(f2tf32(w.x), f2tf32(w.y), f2tf32(w.z), f2tf32(w.w));
        }
    }
    __syncthreads();

    // ---- GEMM2: D2[64,32] = A2 @ W2^T; warp tile 32m x 8n (2m x 4n) ----
    {
        const int m2 = (wid & 1) * 32;
        const int n0 = (wid >> 1) * 8;
        float acc2[2][4];
        #pragma unroll
        for (int mt = 0; mt < 2; mt++)
            #pragma unroll
            for (int j = 0; j < 4; j++) acc2[mt][j] = 0.f;

        #pragma unroll 1
        for (int s = 0; s < HID / 8; s++) {
            const int k0 = s * 8;
            uint32_t af[2][4];
            #pragma unroll
            for (int mt = 0; mt < 2; mt++) {
                const int r = m2 + mt * 16;
                af[mt][0] = Asm[(r + g)     * SAW + k0 + t];
                af[mt][1] = Asm[(r + g + 8) * SAW + k0 + t];
                af[mt][2] = Asm[(r + g)     * SAW + k0 + t + 4];
                af[mt][3] = Asm[(r + g + 8) * SAW + k0 + t + 4];
            }
            const int n = n0 + g;
            const uint32_t b0  = Bsm[n * SW2 + k0 + t];
            const uint32_t b1r = Bsm[n * SW2 + k0 + t + 4];
            mma8(acc2[0], af[0], b0, b1r);
            mma8(acc2[1], af[1], b0, b1r);
        }

        // ---- Epilogue2: out = D2 + b2 ----
        const int col = n0 + t * 2;
        const float bi0 = sb2[col], bi1 = sb2[col + 1];
        #pragma unroll
        for (int mt = 0; mt < 2; mt++) {
            const int mr0 = tile * TILE_M + m2 + mt * 16 + g;
            float* c = acc2[mt];
            if (mr0 < E)
                *(float2*)(out + (size_t)mr0 * NCLS + col) =
                    make_float2(c[0] + bi0, c[1] + bi1);
            if (mr0 + 8 < E)
                *(float2*)(out + (size_t)(mr0 + 8) * NCLS + col) =
                    make_float2(c[2] + bi0, c[3] + bi1);
        }
    }
}

// ============================================================================
extern "C" void kernel_launch(void* const* d_in, const int* in_sizes, int n_in,
                              void* d_out, int out_size) {
    const float* emb  = (const float*)d_in[0];
    const void*  eidx = d_in[1];
    const float* W1   = (const float*)d_in[2];
    const float* b1   = (const float*)d_in[3];
    const float* W2   = (const float*)d_in[4];
    const float* b2   = (const float*)d_in[5];
    float* out = (float*)d_out;

    const int E = in_sizes[1] / 2;
    const int tiles = (E + TILE_M - 1) / TILE_M;

    cudaFuncSetAttribute(edge_mlp_kernel,
                         cudaFuncAttributeMaxDynamicSharedMemorySize, SM_TOTAL);

    detect_idx_kernel<<<1, 1>>>((const unsigned int*)eidx);
    edge_mlp_kernel<<<tiles, 256, SM_TOTAL>>>(emb, eidx, W1, b1, W2, b2, out, E);
}

// round 6
// speedup vs baseline: 2.1854x; 2.1854x over previous
#include <cuda_runtime.h>
#include <cstdint>

// ============================================================================
// EdgeClassifier: out = relu([emb[h], emb[t]] @ W1^T + b1) @ W2^T + b2
// E=500000, D=128, HIDDEN=256, NUM_CLASSES=32, fp32 in/out.
// R5: TILE_M=128, warp tile 64x64 (fewer LDS bytes/MMA), W1/W2 pre-converted
// to tf32 in __device__ scratch, cp.async double-buffered W1 chunk pipeline.
// ============================================================================

#define TILE_M 128
#define DIMD   128
#define HID    256
#define NCLS   32
#define KC     32                      // W1 K-chunk width
#define NCHUNK (HID / KC)              // 8

#define SAW 260                        // A row stride (words), %32==4 -> conflict-free
#define SBW 36                         // W1 chunk row stride,  %32==4 -> conflict-free
#define SW2 268                        // W2 row stride,        %32==12 -> conflict-free

#define W1CH_WORDS (256 * SBW)         // 9216 words / chunk (pre-padded)
#define W2_WORDS   (NCLS * SW2)        // 8576 words (pre-padded)

// SMEM byte offsets
#define SM_B1    0
#define SM_B2    1024
#define SM_A     2048                              // 128 x 260 x 4 = 133120
#define SM_BUF0  (SM_A + TILE_M * SAW * 4)         // 135168
#define SM_BUF1  (SM_BUF0 + W1CH_WORDS * 4)        // +36864
#define SM_TOTAL (SM_BUF1 + W1CH_WORDS * 4)        // 208896

__device__ __align__(16) uint32_t g_w1t[NCHUNK * W1CH_WORDS];
__device__ __align__(16) uint32_t g_w2t[W2_WORDS];
__device__ int g_is64;

__device__ __forceinline__ uint32_t f2tf32(float f) {
    uint32_t r;
    asm("cvt.rna.tf32.f32 %0, %1;" : "=r"(r) : "f"(f));
    return r;
}
__device__ __forceinline__ uint32_t smem_u32(const void* p) {
    uint32_t a;
    asm("{ .reg .u64 t; cvta.to.shared.u64 t, %1; cvt.u32.u64 %0, t; }"
        : "=r"(a) : "l"(p));
    return a;
}
__device__ __forceinline__ void cp16(uint32_t dst, const void* src) {
    asm volatile("cp.async.cg.shared.global [%0], [%1], 16;"
                 :: "r"(dst), "l"(src) : "memory");
}
__device__ __forceinline__ void cp_commit() {
    asm volatile("cp.async.commit_group;" ::: "memory");
}
template <int N>
__device__ __forceinline__ void cp_wait() {
    asm volatile("cp.async.wait_group %0;" :: "n"(N) : "memory");
}
__device__ __forceinline__ void mma8(float* c, const uint32_t* a,
                                     uint32_t b0, uint32_t b1) {
    asm volatile(
        "mma.sync.aligned.m16n8k8.row.col.f32.tf32.tf32.f32 "
        "{%0,%1,%2,%3}, {%4,%5,%6,%7}, {%8,%9}, {%0,%1,%2,%3};"
        : "+f"(c[0]), "+f"(c[1]), "+f"(c[2]), "+f"(c[3])
        : "r"(a[0]), "r"(a[1]), "r"(a[2]), "r"(a[3]), "r"(b0), "r"(b1));
}

// ---- pre-kernels (run every launch; deterministic, alloc-free) -------------
__global__ void detect_idx_kernel(const unsigned int* __restrict__ p) {
    unsigned int acc = 0;
    for (int i = 1; i < 256; i += 2) acc |= p[i];
    g_is64 = (acc == 0u) ? 1 : 0;
}

__global__ void preconvert_kernel(const float* __restrict__ W1,
                                  const float* __restrict__ W2) {
    const int i = blockIdx.x * 256 + threadIdx.x;
    if (i < NCHUNK * W1CH_WORDS) {
        const int kc = i / W1CH_WORDS, rem = i % W1CH_WORDS;
        const int row = rem / SBW, col = rem % SBW;
        g_w1t[i] = (col < KC) ? f2tf32(W1[row * HID + kc * KC + col]) : 0u;
    }
    if (i < W2_WORDS) {
        const int row = i / SW2, col = i % SW2;
        g_w2t[i] = (col < HID) ? f2tf32(W2[row * HID + col]) : 0u;
    }
}

// ============================================================================
__global__ __launch_bounds__(256, 1)
void edge_mlp_kernel(const float* __restrict__ emb,
                     const void*  __restrict__ eidx,
                     const float* __restrict__ b1,
                     const float* __restrict__ b2,
                     float* __restrict__ out,
                     int E) {
    extern __shared__ char smem[];
    float*    sb1 = (float*)(smem + SM_B1);
    float*    sb2 = (float*)(smem + SM_B2);
    uint32_t* Asm = (uint32_t*)(smem + SM_A);
    const uint32_t sb = smem_u32(smem);

    const int tid  = threadIdx.x;
    const int wid  = tid >> 5;
    const int lane = tid & 31;
    const int g    = lane >> 2;
    const int t    = lane & 3;
    const int tile = blockIdx.x;
    const int is64 = g_is64;

    sb1[tid] = b1[tid];
    if (tid < NCLS) sb2[tid] = b2[tid];

    // Prologue: async-stage W1 chunks 0,1 while we gather A.
    {
        const uint32_t d0 = sb + SM_BUF0, d1 = sb + SM_BUF1;
        #pragma unroll
        for (int s = 0; s < W1CH_WORDS / 4; s += 256) {
            cp16(d0 + (s + tid) * 16, g_w1t + (s + tid) * 4);
        }
        cp_commit();
        #pragma unroll
        for (int s = 0; s < W1CH_WORDS / 4; s += 256) {
            cp16(d1 + (s + tid) * 16, g_w1t + W1CH_WORDS + (s + tid) * 4);
        }
        cp_commit();
    }

    // ---- Gather A[128][256] (tf32, RNA) ----
    for (int rh = wid; rh < 2 * TILE_M; rh += 8) {
        const int r = rh >> 1, half = rh & 1;
        const int e = tile * TILE_M + r;
        float4 v = make_float4(0.f, 0.f, 0.f, 0.f);
        if (e < E) {
            const long long ofs = half ? (long long)E + e : (long long)e;
            const long long node = is64 ? ((const long long*)eidx)[ofs]
                                        : (long long)((const int*)eidx)[ofs];
            v = ((const float4*)(emb + node * DIMD))[lane];
        }
        *(uint4*)(Asm + r * SAW + half * 128 + lane * 4) =
            make_uint4(f2tf32(v.x), f2tf32(v.y), f2tf32(v.z), f2tf32(v.w));
    }

    // ---- GEMM1: D1[128,256] = A @ W1^T; warp tile 64x64 (2m x 4n warps) ----
    const int mwb = (wid & 1) * 64;     // warp m-base
    const int nwb = (wid >> 1) * 64;    // warp n-base

    float acc[4][8][4];
    #pragma unroll
    for (int mt = 0; mt < 4; mt++)
        #pragma unroll
        for (int nt = 0; nt < 8; nt++)
            #pragma unroll
            for (int j = 0; j < 4; j++) acc[mt][nt][j] = 0.f;

    #pragma unroll 1
    for (int kc = 0; kc < NCHUNK; kc++) {
        cp_wait<1>();          // chunk kc resident
        __syncthreads();       // + A tile visible on kc==0

        const uint32_t* Bsm =
            (const uint32_t*)(smem + ((kc & 1) ? SM_BUF1 : SM_BUF0));

        #pragma unroll
        for (int s = 0; s < KC / 8; s++) {
            const int k0 = s * 8;
            const int ka = kc * KC + k0;
            uint32_t af[4][4];
            #pragma unroll
            for (int mt = 0; mt < 4; mt++) {
                const int r = mwb + mt * 16;
                af[mt][0] = Asm[(r + g)     * SAW + ka + t];
                af[mt][1] = Asm[(r + g + 8) * SAW + ka + t];
                af[mt][2] = Asm[(r + g)     * SAW + ka + t + 4];
                af[mt][3] = Asm[(r + g + 8) * SAW + ka + t + 4];
            }
            #pragma unroll
            for (int nt = 0; nt < 8; nt++) {
                const int n = nwb + nt * 8 + g;
                const uint32_t b0  = Bsm[n * SBW + k0 + t];
                const uint32_t b1r = Bsm[n * SBW + k0 + t + 4];
                #pragma unroll
                for (int mt = 0; mt < 4; mt++) mma8(acc[mt][nt], af[mt], b0, b1r);
            }
        }
        __syncthreads();       // all warps done with buf[kc&1]

        if (kc < NCHUNK - 2) {
            // stage chunk kc+2 into the buffer just released
            const uint32_t d = sb + ((kc & 1) ? SM_BUF1 : SM_BUF0);
            const uint32_t* src = g_w1t + (kc + 2) * W1CH_WORDS;
            #pragma unroll
            for (int s = 0; s < W1CH_WORDS / 4; s += 256)
                cp16(d + (s + tid) * 16, src + (s + tid) * 4);
            cp_commit();
        } else if (kc == NCHUNK - 2) {
            // buf0 is free: prefetch W2 (overlaps chunk-7 MMA)
            const uint32_t d = sb + SM_BUF0;
            for (int s = tid; s < W2_WORDS / 4; s += 256)
                cp16(d + s * 16, g_w2t + s * 4);
            cp_commit();
        }
    }

    // ---- Epilogue1: A2 = tf32(relu(D1 + b1)) in place over A ----
    #pragma unroll
    for (int mt = 0; mt < 4; mt++) {
        #pragma unroll
        for (int nt = 0; nt < 8; nt++) {
            const int r0  = mwb + mt * 16 + g;
            const int col = nwb + nt * 8 + t * 2;
            const float bi0 = sb1[col], bi1 = sb1[col + 1];
            float* c = acc[mt][nt];
            uint2 lo, hi;
            lo.x = f2tf32(fmaxf(c[0] + bi0, 0.f));
            lo.y = f2tf32(fmaxf(c[1] + bi1, 0.f));
            hi.x = f2tf32(fmaxf(c[2] + bi0, 0.f));
            hi.y = f2tf32(fmaxf(c[3] + bi1, 0.f));
            *(uint2*)(Asm + r0 * SAW + col)       = lo;
            *(uint2*)(Asm + (r0 + 8) * SAW + col) = hi;
        }
    }
    cp_wait<0>();              // W2 resident in buf0
    __syncthreads();

    // ---- GEMM2: D2[128,32] = A2 @ W2^T; warp tile 64m x 8n (2m x 4n) ----
    {
        const uint32_t* Wsm = (const uint32_t*)(smem + SM_BUF0);
        const int n0 = (wid >> 1) * 8;
        float acc2[4][4];
        #pragma unroll
        for (int mt = 0; mt < 4; mt++)
            #pragma unroll
            for (int j = 0; j < 4; j++) acc2[mt][j] = 0.f;

        #pragma unroll 4
        for (int s = 0; s < HID / 8; s++) {
            const int k0 = s * 8;
            const int n = n0 + g;
            const uint32_t b0  = Wsm[n * SW2 + k0 + t];
            const uint32_t b1r = Wsm[n * SW2 + k0 + t + 4];
            #pragma unroll
            for (int mt = 0; mt < 4; mt++) {
                const int r = mwb + mt * 16;
                uint32_t af[4];
                af[0] = Asm[(r + g)     * SAW + k0 + t];
                af[1] = Asm[(r + g + 8) * SAW + k0 + t];
                af[2] = Asm[(r + g)     * SAW + k0 + t + 4];
                af[3] = Asm[(r + g + 8) * SAW + k0 + t + 4];
                mma8(acc2[mt], af, b0, b1r);
            }
        }

        // ---- Epilogue2: out = D2 + b2 ----
        const int col = n0 + t * 2;
        const float bi0 = sb2[col], bi1 = sb2[col + 1];
        #pragma unroll
        for (int mt = 0; mt < 4; mt++) {
            const int mr0 = tile * TILE_M + mwb + mt * 16 + g;
            float* c = acc2[mt];
            if (mr0 < E)
                *(float2*)(out + (size_t)mr0 * NCLS + col) =
                    make_float2(c[0] + bi0, c[1] + bi1);
            if (mr0 + 8 < E)
                *(float2*)(out + (size_t)(mr0 + 8) * NCLS + col) =
                    make_float2(c[2] + bi0, c[3] + bi1);
        }
    }
}

// ============================================================================
extern "C" void kernel_launch(void* const* d_in, const int* in_sizes, int n_in,
                              void* d_out, int out_size) {
    const float* emb  = (const float*)d_in[0];
    const void*  eidx = d_in[1];
    const float* W1   = (const float*)d_in[2];
    const float* b1   = (const float*)d_in[3];
    const float* W2   = (const float*)d_in[4];
    const float* b2   = (const float*)d_in[5];
    float* out = (float*)d_out;

    const int E = in_sizes[1] / 2;
    const int tiles = (E + TILE_M - 1) / TILE_M;

    cudaFuncSetAttribute(edge_mlp_kernel,
                         cudaFuncAttributeMaxDynamicSharedMemorySize, SM_TOTAL);

    detect_idx_kernel<<<1, 1>>>((const unsigned int*)eidx);
    preconvert_kernel<<<(NCHUNK * W1CH_WORDS + 255) / 256, 256>>>(W1, W2);
    edge_mlp_kernel<<<tiles, 256, SM_TOTAL>>>(emb, eidx, b1, b2, out, E);
}

// round 7
// speedup vs baseline: 2.4889x; 1.1388x over previous
#include <cuda_runtime.h>
#include <cstdint>

// ============================================================================
// EdgeClassifier: out = relu([emb[h], emb[t]] @ W1^T + b1) @ W2^T + b2
// E=500000, D=128, HIDDEN=256, NUM_CLASSES=32, fp32 in/out.
// R7: GEMM2 computed from GEMM1 accumulators (shuffle-based C->A fragment
// conversion + per-warp K=64 partials + smem cross-warp reduce). A2 round
// trip through shared memory eliminated.
// ============================================================================

#define TILE_M 128
#define DIMD   128
#define HID    256
#define NCLS   32
#define KC     32
#define NCHUNK (HID / KC)              // 8

#define SAW 260                        // A row stride (words), %32==4 conflict-free
#define SBW 36                         // W1 chunk row stride,  %32==4 conflict-free
#define SW2 268                        // W2 row stride,        %32==12 conflict-free

#define W1CH_WORDS (256 * SBW)         // 9216 words / chunk
#define W2_WORDS   (NCLS * SW2)        // 8576 words

// SMEM byte offsets
#define SM_B1    0
#define SM_B2    1024
#define SM_A     2048                              // 128 x 260 x 4 = 133120
#define SM_BUF0  (SM_A + TILE_M * SAW * 4)
#define SM_BUF1  (SM_BUF0 + W1CH_WORDS * 4)
#define SM_TOTAL (SM_BUF1 + W1CH_WORDS * 4)        // 208896

__device__ __align__(16) uint32_t g_w1t[NCHUNK * W1CH_WORDS];
__device__ __align__(16) uint32_t g_w2t[W2_WORDS];
__device__ int g_is64;

__device__ __forceinline__ uint32_t f2tf32(float f) {
    uint32_t r;
    asm("cvt.rna.tf32.f32 %0, %1;" : "=r"(r) : "f"(f));
    return r;
}
__device__ __forceinline__ uint32_t smem_u32(const void* p) {
    uint32_t a;
    asm("{ .reg .u64 t; cvta.to.shared.u64 t, %1; cvt.u32.u64 %0, t; }"
        : "=r"(a) : "l"(p));
    return a;
}
__device__ __forceinline__ void cp16(uint32_t dst, const void* src) {
    asm volatile("cp.async.cg.shared.global [%0], [%1], 16;"
                 :: "r"(dst), "l"(src) : "memory");
}
__device__ __forceinline__ void cp_commit() {
    asm volatile("cp.async.commit_group;" ::: "memory");
}
template <int N>
__device__ __forceinline__ void cp_wait() {
    asm volatile("cp.async.wait_group %0;" :: "n"(N) : "memory");
}
__device__ __forceinline__ void mma8(float* c, const uint32_t* a,
                                     uint32_t b0, uint32_t b1) {
    asm volatile(
        "mma.sync.aligned.m16n8k8.row.col.f32.tf32.tf32.f32 "
        "{%0,%1,%2,%3}, {%4,%5,%6,%7}, {%8,%9}, {%0,%1,%2,%3};"
        : "+f"(c[0]), "+f"(c[1]), "+f"(c[2]), "+f"(c[3])
        : "r"(a[0]), "r"(a[1]), "r"(a[2]), "r"(a[3]), "r"(b0), "r"(b1));
}

// ---- pre-kernel: idx-width detect + weight tf32 pre-convert (one launch) ---
__global__ void prep_kernel(const float* __restrict__ W1,
                            const float* __restrict__ W2,
                            const unsigned int* __restrict__ p) {
    if (blockIdx.x == 0) {
        unsigned v = (threadIdx.x < 128) ? p[2 * threadIdx.x + 1] : 0u;
        int anynz = __syncthreads_or(v != 0u);
        if (threadIdx.x == 0) g_is64 = anynz ? 0 : 1;
    }
    const int i = blockIdx.x * 256 + threadIdx.x;
    if (i < NCHUNK * W1CH_WORDS) {
        const int kc = i / W1CH_WORDS, rem = i % W1CH_WORDS;
        const int row = rem / SBW, col = rem % SBW;
        g_w1t[i] = (col < KC) ? f2tf32(W1[row * HID + kc * KC + col]) : 0u;
    }
    if (i < W2_WORDS) {
        const int row = i / SW2, col = i % SW2;
        g_w2t[i] = (col < HID) ? f2tf32(W2[row * HID + col]) : 0u;
    }
}

// ============================================================================
__global__ __launch_bounds__(256, 1)
void edge_mlp_kernel(const float* __restrict__ emb,
                     const void*  __restrict__ eidx,
                     const float* __restrict__ b1,
                     const float* __restrict__ b2,
                     float* __restrict__ out,
                     int E) {
    extern __shared__ char smem[];
    float*    sb1 = (float*)(smem + SM_B1);
    float*    sb2 = (float*)(smem + SM_B2);
    uint32_t* Asm = (uint32_t*)(smem + SM_A);
    const uint32_t sb = smem_u32(smem);

    const int tid  = threadIdx.x;
    const int wid  = tid >> 5;
    const int lane = tid & 31;
    const int g    = lane >> 2;
    const int t    = lane & 3;
    const int tile = blockIdx.x;
    const int is64 = g_is64;

    sb1[tid] = b1[tid];
    if (tid < NCLS) sb2[tid] = b2[tid];

    // Prologue: async-stage W1 chunks 0,1.
    {
        const uint32_t d0 = sb + SM_BUF0, d1 = sb + SM_BUF1;
        #pragma unroll
        for (int s = 0; s < W1CH_WORDS / 4; s += 256)
            cp16(d0 + (s + tid) * 16, g_w1t + (s + tid) * 4);
        cp_commit();
        #pragma unroll
        for (int s = 0; s < W1CH_WORDS / 4; s += 256)
            cp16(d1 + (s + tid) * 16, g_w1t + W1CH_WORDS + (s + tid) * 4);
        cp_commit();
    }

    // ---- Gather A[128][256]: warp handles one half (head/tail), rows
    //      r = (wid>>1) + 4j. Indices preloaded lane-parallel, shfl-broadcast.
    {
        const int half  = wid & 1;
        const int rbase = wid >> 1;
        long long node_l = -1;
        {
            const int r = rbase + 4 * lane;
            const int e = tile * TILE_M + r;
            if (e < E) {
                const long long ofs = half ? (long long)E + e : (long long)e;
                node_l = is64 ? ((const long long*)eidx)[ofs]
                              : (long long)((const int*)eidx)[ofs];
            }
        }
        #pragma unroll 4
        for (int j = 0; j < 32; j++) {
            const int r = rbase + 4 * j;
            const long long node = __shfl_sync(0xffffffffu, node_l, j);
            float4 v = make_float4(0.f, 0.f, 0.f, 0.f);
            if (node >= 0) v = ((const float4*)(emb + node * DIMD))[lane];
            *(uint4*)(Asm + r * SAW + half * 128 + lane * 4) =
                make_uint4(f2tf32(v.x), f2tf32(v.y), f2tf32(v.z), f2tf32(v.w));
        }
    }

    // ---- GEMM1: D1[128,256] = A @ W1^T; warp tile 64x64 (2m x 4n warps) ----
    const int mwb = (wid & 1) * 64;
    const int nwb = (wid >> 1) * 64;

    float acc[4][8][4];
    #pragma unroll
    for (int mt = 0; mt < 4; mt++)
        #pragma unroll
        for (int nt = 0; nt < 8; nt++)
            #pragma unroll
            for (int j = 0; j < 4; j++) acc[mt][nt][j] = 0.f;

    #pragma unroll 1
    for (int kc = 0; kc < NCHUNK; kc++) {
        cp_wait<1>();
        __syncthreads();

        const uint32_t* Bsm =
            (const uint32_t*)(smem + ((kc & 1) ? SM_BUF1 : SM_BUF0));

        #pragma unroll
        for (int s = 0; s < KC / 8; s++) {
            const int k0 = s * 8;
            const int ka = kc * KC + k0;
            uint32_t af[4][4];
            #pragma unroll
            for (int mt = 0; mt < 4; mt++) {
                const int r = mwb + mt * 16;
                af[mt][0] = Asm[(r + g)     * SAW + ka + t];
                af[mt][1] = Asm[(r + g + 8) * SAW + ka + t];
                af[mt][2] = Asm[(r + g)     * SAW + ka + t + 4];
                af[mt][3] = Asm[(r + g + 8) * SAW + ka + t + 4];
            }
            #pragma unroll
            for (int nt = 0; nt < 8; nt++) {
                const int n = nwb + nt * 8 + g;
                const uint32_t b0  = Bsm[n * SBW + k0 + t];
                const uint32_t b1r = Bsm[n * SBW + k0 + t + 4];
                #pragma unroll
                for (int mt = 0; mt < 4; mt++) mma8(acc[mt][nt], af[mt], b0, b1r);
            }
        }
        __syncthreads();

        if (kc < NCHUNK - 2) {
            const uint32_t d = sb + ((kc & 1) ? SM_BUF1 : SM_BUF0);
            const uint32_t* src = g_w1t + (kc + 2) * W1CH_WORDS;
            #pragma unroll
            for (int s = 0; s < W1CH_WORDS / 4; s += 256)
                cp16(d + (s + tid) * 16, src + (s + tid) * 4);
            cp_commit();
        } else if (kc == NCHUNK - 2) {
            const uint32_t d = sb + SM_BUF0;     // buf0 free: prefetch W2
            for (int s = tid; s < W2_WORDS / 4; s += 256)
                cp16(d + s * 16, g_w2t + s * 4);
            cp_commit();
        }
    }

    // ---- GEMM2 from registers: per-warp K=64 partials -----------------------
    // h = tf32(relu(D1 + b1)) in regs; C-frag (g,2t)(g,2t+1) -> A-frag
    // (g,t)(g,t+4) via intra-quad shuffles; then m16n8k8 against W2 frags.
    cp_wait<0>();                        // W2 resident in BUF0
    const uint32_t* Wsm = (const uint32_t*)(smem + SM_BUF0);

    float acc2p[4][4][4];
    #pragma unroll
    for (int mt = 0; mt < 4; mt++)
        #pragma unroll
        for (int n2b = 0; n2b < 4; n2b++)
            #pragma unroll
            for (int j = 0; j < 4; j++) acc2p[mt][n2b][j] = 0.f;

    const int srcA = (lane & ~3) | (t >> 1);
    const int srcB = srcA + 2;
    const bool odd = (t & 1) != 0;

    #pragma unroll
    for (int nt = 0; nt < 8; nt++) {
        const int colb = nwb + nt * 8;
        const float bi0 = sb1[colb + 2 * t];
        const float bi1 = sb1[colb + 2 * t + 1];
        uint32_t bf[4][2];
        #pragma unroll
        for (int n2b = 0; n2b < 4; n2b++) {
            bf[n2b][0] = Wsm[(n2b * 8 + g) * SW2 + colb + t];
            bf[n2b][1] = Wsm[(n2b * 8 + g) * SW2 + colb + t + 4];
        }
        #pragma unroll
        for (int mt = 0; mt < 4; mt++) {
            const float* c = acc[mt][nt];
            const uint32_t h0 = f2tf32(fmaxf(c[0] + bi0, 0.f));
            const uint32_t h1 = f2tf32(fmaxf(c[1] + bi1, 0.f));
            const uint32_t h2 = f2tf32(fmaxf(c[2] + bi0, 0.f));
            const uint32_t h3 = f2tf32(fmaxf(c[3] + bi1, 0.f));
            const uint32_t x0 = __shfl_sync(0xffffffffu, h0, srcA);
            const uint32_t x1 = __shfl_sync(0xffffffffu, h1, srcA);
            const uint32_t x2 = __shfl_sync(0xffffffffu, h2, srcA);
            const uint32_t x3 = __shfl_sync(0xffffffffu, h3, srcA);
            const uint32_t y0 = __shfl_sync(0xffffffffu, h0, srcB);
            const uint32_t y1 = __shfl_sync(0xffffffffu, h1, srcB);
            const uint32_t y2 = __shfl_sync(0xffffffffu, h2, srcB);
            const uint32_t y3 = __shfl_sync(0xffffffffu, h3, srcB);
            uint32_t a[4];
            a[0] = odd ? x1 : x0;   // (g,   t)
            a[1] = odd ? x3 : x2;   // (g+8, t)
            a[2] = odd ? y1 : y0;   // (g,   t+4)
            a[3] = odd ? y3 : y2;   // (g+8, t+4)
            #pragma unroll
            for (int n2b = 0; n2b < 4; n2b++)
                mma8(acc2p[mt][n2b], a, bf[n2b][0], bf[n2b][1]);
        }
    }

    // ---- Cross-warp K-reduce via scratch over dead A region ---------------
    // layout: word = wid*2048 + reg*32 + lane, reg = mt*16 + n2b*4 + ci
    {
        float* scr = (float*)(smem + SM_A);
        #pragma unroll
        for (int mt = 0; mt < 4; mt++)
            #pragma unroll
            for (int n2b = 0; n2b < 4; n2b++)
                #pragma unroll
                for (int ci = 0; ci < 4; ci++)
                    scr[wid * 2048 + (mt * 16 + n2b * 4 + ci) * 32 + lane] =
                        acc2p[mt][n2b][ci];
        __syncthreads();

        const int mgrp = wid & 1;       // producer warps kw*2+mgrp share rows
        const int wq   = wid >> 1;      // this warp reduces mt-slice wq
        #pragma unroll
        for (int n2b = 0; n2b < 4; n2b++) {
            float s[4];
            #pragma unroll
            for (int ci = 0; ci < 4; ci++) {
                const int reg = wq * 16 + n2b * 4 + ci;
                float v = scr[(0 * 2 + mgrp) * 2048 + reg * 32 + lane];
                v += scr[(1 * 2 + mgrp) * 2048 + reg * 32 + lane];
                v += scr[(2 * 2 + mgrp) * 2048 + reg * 32 + lane];
                v += scr[(3 * 2 + mgrp) * 2048 + reg * 32 + lane];
                s[ci] = v;
            }
            const int cc = n2b * 8 + 2 * t;
            const float bz0 = sb2[cc], bz1 = sb2[cc + 1];
            const int r0 = tile * TILE_M + mgrp * 64 + wq * 16 + g;
            if (r0 < E)
                *(float2*)(out + (size_t)r0 * NCLS + cc) =
                    make_float2(s[0] + bz0, s[1] + bz1);
            if (r0 + 8 < E)
                *(float2*)(out + (size_t)(r0 + 8) * NCLS + cc) =
                    make_float2(s[2] + bz0, s[3] + bz1);
        }
    }
}

// ============================================================================
extern "C" void kernel_launch(void* const* d_in, const int* in_sizes, int n_in,
                              void* d_out, int out_size) {
    const float* emb  = (const float*)d_in[0];
    const void*  eidx = d_in[1];
    const float* W1   = (const float*)d_in[2];
    const float* b1   = (const float*)d_in[3];
    const float* W2   = (const float*)d_in[4];
    const float* b2   = (const float*)d_in[5];
    float* out = (float*)d_out;

    const int E = in_sizes[1] / 2;
    const int tiles = (E + TILE_M - 1) / TILE_M;

    cudaFuncSetAttribute(edge_mlp_kernel,
                         cudaFuncAttributeMaxDynamicSharedMemorySize, SM_TOTAL);

    prep_kernel<<<(NCHUNK * W1CH_WORDS + 255) / 256, 256>>>(
        W1, W2, (const unsigned int*)eidx);
    edge_mlp_kernel<<<tiles, 256, SM_TOTAL>>>(emb, eidx, b1, b2, out, E);
}